// round 6
// baseline (speedup 1.0000x reference)
#include <cuda_runtime.h>
#include <cstdint>

#define D    768
#define DV   (D / 4)    // 192 float4 per row
#define E    8
#define RB   4          // rows per warp-batch
#define NJ   12         // k-iterations (16 float4 columns per iter per half-warp)
#define NS   3          // cp.async pipeline stages
#define WRP  8          // warps per CTA

typedef unsigned long long ull;

// packed 2-wide fp32 FMA: d = a*b + d
__device__ __forceinline__ void ffma2(ull& d, ull a, ull b) {
    asm("fma.rn.f32x2 %0, %1, %2, %0;" : "+l"(d) : "l"(a), "l"(b));
}
// broadcast one f32 into both halves of a b64
__device__ __forceinline__ ull bcast2(float x) {
    ull r;
    asm("mov.b64 %0, {%1, %1};" : "=l"(r) : "r"(__float_as_uint(x)));
    return r;
}
__device__ __forceinline__ uint32_t s2u(const void* p) {
    uint32_t a;
    asm("{ .reg .u64 t; cvta.to.shared.u64 t, %1; cvt.u32.u64 %0, t; }"
        : "=r"(a) : "l"(p));
    return a;
}
__device__ __forceinline__ void cpa16(uint32_t s, const float4* g) {
    asm volatile("cp.async.cg.shared.global [%0], [%1], 16;" :: "r"(s), "l"(g));
}
#define CP_COMMIT() asm volatile("cp.async.commit_group;")
#define CP_WAIT1()  asm volatile("cp.async.wait_group 1;")
#define COMP(v, c) ((c) == 0 ? (v).x : (c) == 1 ? (v).y : (c) == 2 ? (v).z : (v).w)

__global__ __launch_bounds__(256, 4)
void router_kernel(const float* __restrict__ h,
                   const float* __restrict__ gw,
                   const float* __restrict__ gb,
                   float* __restrict__ out, int B) {
    extern __shared__ float4 smem[];
    float4* ws2  = smem;                 // 8*DV float4 = 24 KB (packed weights)
    float4* xbuf = smem + 8 * DV;        // WRP*NS*64 float4 = 24 KB (h staging)
    float*  b_sh = (float*)(xbuf + WRP * NS * 64);   // 8 floats

    // w transposed+packed: ws2[(c*2+g)*DV + k4] = float4 of experts {4g..4g+3},
    // scalar column (4*k4 + c).
    for (int i = threadIdx.x; i < 8 * DV; i += blockDim.x) {
        const int k4 = i % DV;
        const int cg = i / DV;
        const int c  = cg >> 1;
        const int g  = cg & 1;
        const int col = 4 * k4 + c;
        ws2[i] = make_float4(gw[(4 * g + 0) * D + col],
                             gw[(4 * g + 1) * D + col],
                             gw[(4 * g + 2) * D + col],
                             gw[(4 * g + 3) * D + col]);
    }
    if (threadIdx.x < E) b_sh[threadIdx.x] = gb[threadIdx.x];
    __syncthreads();

    const ulonglong2* wsu = reinterpret_cast<const ulonglong2*>(ws2);

    const int lane   = threadIdx.x & 31;
    const int half   = lane >> 4;        // 0: rows {0,1}, 1: rows {2,3}
    const int kl     = lane & 15;        // k-slot within half-warp
    const int warp   = threadIdx.x >> 5;
    const int gwarp  = blockIdx.x * WRP + warp;
    const int nwarps = gridDim.x * WRP;
    const int nbatch = B / RB;

    // thread-private staging slots: rows (2*half+0) and (2*half+1), slot kl
    float4* xw = xbuf + warp * (NS * 64);
    const uint32_t xs0 = s2u(xw) + (uint32_t)((2 * half + 0) * 16 + kl) * 16u;
    const uint32_t xs1 = s2u(xw) + (uint32_t)((2 * half + 1) * 16 + kl) * 16u;
    const float4*  xr0 = xw + (2 * half + 0) * 16 + kl;
    const float4*  xr1 = xw + (2 * half + 1) * 16 + kl;

    float* out_idx = out;                       // [B,2] indices (as float)
    float* out_wt  = out + (size_t)2 * B;       // [B,2] weights
    float* out_lg  = out + (size_t)4 * B;       // [B,8] logits

    const float4* h4 = reinterpret_cast<const float4*>(h);

    for (int batch = gwarp; batch < nbatch; batch += nwarps) {
        const int row0 = batch * RB;
        const float4* g0 = h4 + (size_t)(row0 + 2 * half) * DV + kl;  // row a
        const float4* g1 = g0 + DV;                                    // row a+1

        // prologue: stages for j = 0 .. NS-2
        #pragma unroll
        for (int s = 0; s < NS - 1; s++) {
            cpa16(xs0 + (uint32_t)(s * 1024), g0 + s * 16);
            cpa16(xs1 + (uint32_t)(s * 1024), g1 + s * 16);
            CP_COMMIT();
        }

        // acc2[r][p] packs experts (2p, 2p+1) for local row r (0/1)
        ull acc2[2][4];
        #pragma unroll
        for (int r = 0; r < 2; r++)
            #pragma unroll
            for (int p = 0; p < 4; p++) acc2[r][p] = 0ull;

        #pragma unroll 1
        for (int j = 0; j < NJ; j++) {
            CP_WAIT1();                       // stage j complete (<=1 newer pending)

            const int st = j % NS;
            const float4 x0 = xr0[st * 64];   // LDS.128, thread-private
            const float4 x1 = xr1[st * 64];

            // issue stage j+NS-1; empty commit keeps group counting aligned
            if (j < NJ - (NS - 1)) {
                const int jn = j + NS - 1;
                cpa16(xs0 + (uint32_t)(((jn % NS) * 1024)), g0 + jn * 16);
                cpa16(xs1 + (uint32_t)(((jn % NS) * 1024)), g1 + jn * 16);
            }
            CP_COMMIT();

            const int k4 = j * 16 + kl;
            #pragma unroll
            for (int c = 0; c < 4; c++) {
                // both half-warps read same addresses -> LDS broadcast
                const ulonglong2 wg0 = wsu[(c * 2 + 0) * DV + k4]; // experts 0-3
                const ulonglong2 wg1 = wsu[(c * 2 + 1) * DV + k4]; // experts 4-7
                {
                    const ull xb = bcast2(COMP(x0, c));
                    ffma2(acc2[0][0], wg0.x, xb); ffma2(acc2[0][1], wg0.y, xb);
                    ffma2(acc2[0][2], wg1.x, xb); ffma2(acc2[0][3], wg1.y, xb);
                }
                {
                    const ull xb = bcast2(COMP(x1, c));
                    ffma2(acc2[1][0], wg0.x, xb); ffma2(acc2[1][1], wg0.y, xb);
                    ffma2(acc2[1][2], wg1.x, xb); ffma2(acc2[1][3], wg1.y, xb);
                }
            }
        }

        // unpack to 16 scalars: v[r*8 + e] for local rows r in {0,1}
        float v[16];
        #pragma unroll
        for (int r = 0; r < 2; r++)
            #pragma unroll
            for (int p = 0; p < 4; p++) {
                uint32_t lo, hi;
                asm("mov.b64 {%0, %1}, %2;" : "=r"(lo), "=r"(hi) : "l"(acc2[r][p]));
                v[r * E + 2 * p]     = __uint_as_float(lo);
                v[r * E + 2 * p + 1] = __uint_as_float(hi);
            }

        // Butterfly transpose-reduce within each 16-lane half (offsets 8..1):
        // afterwards lane l holds the full sum of local index (l & 15).
        #pragma unroll
        for (int off = 8; off >= 1; off >>= 1) {
            const bool up = (kl & off) != 0;
            #pragma unroll
            for (int i = 0; i < off; i++) {
                float send = up ? v[i] : v[i + off];
                float recv = __shfl_xor_sync(0xffffffffu, send, off);
                v[i] = (up ? v[i + off] : v[i]) + recv;
            }
        }

        // lane l -> row = row0 + (l>>3), expert e = l&7
        const int e   = lane & 7;
        const int row = row0 + (lane >> 3);
        const float logit = v[0] + b_sh[e];

        out_lg[(size_t)row * E + e] = logit;     // 32 consecutive floats/warp

        float lv[8];
        #pragma unroll
        for (int k = 0; k < 8; k++)
            lv[k] = __shfl_sync(0xffffffffu, logit, (lane & 24) | k);

        if (e == 0) {
            // top-1: strict >, lowest index wins ties (matches lax.top_k)
            int i1 = 0; float v1 = lv[0];
            #pragma unroll
            for (int k = 1; k < 8; k++)
                if (lv[k] > v1) { v1 = lv[k]; i1 = k; }
            int i2 = (i1 == 0) ? 1 : 0; float v2 = lv[i2];
            #pragma unroll
            for (int k = 0; k < 8; k++)
                if (k != i1 && lv[k] > v2) { v2 = lv[k]; i2 = k; }

            const float t  = __expf(v2 - v1);     // <= 1
            const float w1 = 1.0f / (1.0f + t);
            const float w2 = t * w1;

            out_idx[(size_t)row * 2]     = (float)i1;
            out_idx[(size_t)row * 2 + 1] = (float)i2;
            out_wt [(size_t)row * 2]     = w1;
            out_wt [(size_t)row * 2 + 1] = w2;
        }
    }
}

extern "C" void kernel_launch(void* const* d_in, const int* in_sizes, int n_in,
                              void* d_out, int out_size) {
    const float* h  = (const float*)d_in[0];   // [B, 768]
    const float* gw = (const float*)d_in[1];   // [8, 768]
    const float* gb = (const float*)d_in[2];   // [8]
    float* out = (float*)d_out;

    const int B = in_sizes[0] / D;             // 32768

    // smem: 24KB weights + 24KB x staging + bias
    const int smem_bytes = (8 * DV + WRP * NS * 64) * 16 + 64;
    cudaFuncSetAttribute(router_kernel,
                         cudaFuncAttributeMaxDynamicSharedMemorySize, smem_bytes);

    // 592 = 4 x 148: exactly 4 CTAs per SM in a single wave (occ 4).
    const int threads = 256;
    const int blocks  = 592;
    router_kernel<<<blocks, threads, smem_bytes>>>(h, gw, gb, out, B);
}

// round 7
// speedup vs baseline: 1.0327x; 1.0327x over previous
#include <cuda_runtime.h>
#include <cstdint>

#define D    768
#define DV   (D / 4)    // 192 float4 per row
#define E    8
#define RB   4          // rows per warp-batch
#define NJ   12         // k-iterations (16 float4 columns per iter per half-warp)
#define NS   3          // cp.async pipeline stages
#define WRP  8          // warps per CTA

typedef unsigned long long ull;

// packed 2-wide fp32 FMA: d = a*b + d
__device__ __forceinline__ void ffma2(ull& d, ull a, ull b) {
    asm("fma.rn.f32x2 %0, %1, %2, %0;" : "+l"(d) : "l"(a), "l"(b));
}
__device__ __forceinline__ uint32_t s2u(const void* p) {
    uint32_t a;
    asm("{ .reg .u64 t; cvta.to.shared.u64 t, %1; cvt.u32.u64 %0, t; }"
        : "=r"(a) : "l"(p));
    return a;
}
__device__ __forceinline__ void cpa16(uint32_t s, const float4* g) {
    asm volatile("cp.async.cg.shared.global [%0], [%1], 16;" :: "r"(s), "l"(g));
}
#define CP_COMMIT() asm volatile("cp.async.commit_group;")
#define CP_WAIT1()  asm volatile("cp.async.wait_group 1;")

__global__ __launch_bounds__(256, 4)
void router_kernel(const float* __restrict__ h,
                   const float* __restrict__ gw,
                   const float* __restrict__ gb,
                   float* __restrict__ out, int B) {
    extern __shared__ float4 smem[];
    float4* ws   = smem;                 // 8*DV float4 = 24 KB (row-major w copy)
    float4* xbuf = smem + 8 * DV;        // WRP*NS*64 float4 = 24 KB (h staging)
    float*  b_sh = (float*)(xbuf + WRP * NS * 64);   // 8 floats

    // straight row-major copy: ws[e*DV + k4] = (w_e[4k..4k+3])
    const float4* gw4 = reinterpret_cast<const float4*>(gw);
    for (int i = threadIdx.x; i < 8 * DV; i += blockDim.x)
        ws[i] = gw4[i];
    if (threadIdx.x < E) b_sh[threadIdx.x] = gb[threadIdx.x];
    __syncthreads();

    const ulonglong2* wsu = reinterpret_cast<const ulonglong2*>(ws);

    const int lane   = threadIdx.x & 31;
    const int half   = lane >> 4;        // 0: rows {0,1}, 1: rows {2,3}
    const int kl     = lane & 15;        // k-slot within half-warp
    const int warp   = threadIdx.x >> 5;
    const int gwarp  = blockIdx.x * WRP + warp;
    const int nwarps = gridDim.x * WRP;
    const int nbatch = B / RB;

    // thread-private staging slots: rows (2*half+0) and (2*half+1), slot kl
    float4* xw = xbuf + warp * (NS * 64);
    const uint32_t xs0 = s2u(xw) + (uint32_t)((2 * half + 0) * 16 + kl) * 16u;
    const uint32_t xs1 = s2u(xw) + (uint32_t)((2 * half + 1) * 16 + kl) * 16u;
    const ulonglong2* xr0 = reinterpret_cast<const ulonglong2*>(xw + (2 * half + 0) * 16 + kl);
    const ulonglong2* xr1 = reinterpret_cast<const ulonglong2*>(xw + (2 * half + 1) * 16 + kl);

    float* out_idx = out;                       // [B,2] indices (as float)
    float* out_wt  = out + (size_t)2 * B;       // [B,2] weights
    float* out_lg  = out + (size_t)4 * B;       // [B,8] logits

    const float4* h4 = reinterpret_cast<const float4*>(h);

    for (int batch = gwarp; batch < nbatch; batch += nwarps) {
        const int row0 = batch * RB;
        const float4* g0 = h4 + (size_t)(row0 + 2 * half) * DV + kl;  // row a
        const float4* g1 = g0 + DV;                                    // row a+1

        // prologue: stages for j = 0 .. NS-2
        #pragma unroll
        for (int s = 0; s < NS - 1; s++) {
            cpa16(xs0 + (uint32_t)(s * 1024), g0 + s * 16);
            cpa16(xs1 + (uint32_t)(s * 1024), g1 + s * 16);
            CP_COMMIT();
        }

        // acc2[r][e]: low half = even k-pair partial, high half = odd
        ull acc2[2][E];
        #pragma unroll
        for (int r = 0; r < 2; r++)
            #pragma unroll
            for (int e = 0; e < E; e++) acc2[r][e] = 0ull;

        #pragma unroll 1
        for (int j = 0; j < NJ; j++) {
            CP_WAIT1();                        // stage j complete

            const int st = j % NS;
            // x float4 read as two packed k-pairs (LDS.128, thread-private)
            const ulonglong2 xu0 = xr0[st * 64];
            const ulonglong2 xu1 = xr1[st * 64];

            // issue stage j+NS-1; empty commit keeps group counting aligned
            if (j < NJ - (NS - 1)) {
                const int jn = j + NS - 1;
                cpa16(xs0 + (uint32_t)((jn % NS) * 1024), g0 + jn * 16);
                cpa16(xs1 + (uint32_t)((jn % NS) * 1024), g1 + jn * 16);
            }
            CP_COMMIT();

            const int k4 = j * 16 + kl;
            #pragma unroll
            for (int e = 0; e < E; e++) {
                // both half-warps read same address -> LDS broadcast
                const ulonglong2 we = wsu[e * DV + k4];   // (w[4k],w[4k+1]),(w[4k+2],w[4k+3])
                ffma2(acc2[0][e], we.x, xu0.x);
                ffma2(acc2[0][e], we.y, xu0.y);
                ffma2(acc2[1][e], we.x, xu1.x);
                ffma2(acc2[1][e], we.y, xu1.y);
            }
        }

        // unpack + horizontal add: v[r*8 + e] for local rows r in {0,1}
        float v[16];
        #pragma unroll
        for (int r = 0; r < 2; r++)
            #pragma unroll
            for (int e = 0; e < E; e++) {
                uint32_t lo, hi;
                asm("mov.b64 {%0, %1}, %2;" : "=r"(lo), "=r"(hi) : "l"(acc2[r][e]));
                v[r * E + e] = __uint_as_float(lo) + __uint_as_float(hi);
            }

        // Butterfly transpose-reduce within each 16-lane half (offsets 8..1):
        // afterwards lane l holds the full sum of local index (l & 15).
        #pragma unroll
        for (int off = 8; off >= 1; off >>= 1) {
            const bool up = (kl & off) != 0;
            #pragma unroll
            for (int i = 0; i < off; i++) {
                float send = up ? v[i] : v[i + off];
                float recv = __shfl_xor_sync(0xffffffffu, send, off);
                v[i] = (up ? v[i + off] : v[i]) + recv;
            }
        }

        // lane l -> row = row0 + (l>>3), expert e = l&7
        const int e   = lane & 7;
        const int row = row0 + (lane >> 3);
        const float logit = v[0] + b_sh[e];

        out_lg[(size_t)row * E + e] = logit;     // 32 consecutive floats/warp

        float lv[8];
        #pragma unroll
        for (int k = 0; k < 8; k++)
            lv[k] = __shfl_sync(0xffffffffu, logit, (lane & 24) | k);

        if (e == 0) {
            // top-1: strict >, lowest index wins ties (matches lax.top_k)
            int i1 = 0; float v1 = lv[0];
            #pragma unroll
            for (int k = 1; k < 8; k++)
                if (lv[k] > v1) { v1 = lv[k]; i1 = k; }
            int i2 = (i1 == 0) ? 1 : 0; float v2 = lv[i2];
            #pragma unroll
            for (int k = 0; k < 8; k++)
                if (k != i1 && lv[k] > v2) { v2 = lv[k]; i2 = k; }

            const float t  = __expf(v2 - v1);     // <= 1
            const float w1 = 1.0f / (1.0f + t);
            const float w2 = t * w1;

            out_idx[(size_t)row * 2]     = (float)i1;
            out_idx[(size_t)row * 2 + 1] = (float)i2;
            out_wt [(size_t)row * 2]     = w1;
            out_wt [(size_t)row * 2 + 1] = w2;
        }
    }
}

extern "C" void kernel_launch(void* const* d_in, const int* in_sizes, int n_in,
                              void* d_out, int out_size) {
    const float* h  = (const float*)d_in[0];   // [B, 768]
    const float* gw = (const float*)d_in[1];   // [8, 768]
    const float* gb = (const float*)d_in[2];   // [8]
    float* out = (float*)d_out;

    const int B = in_sizes[0] / D;             // 32768

    // smem: 24KB weights + 24KB x staging + bias
    const int smem_bytes = (8 * DV + WRP * NS * 64) * 16 + 64;
    cudaFuncSetAttribute(router_kernel,
                         cudaFuncAttributeMaxDynamicSharedMemorySize, smem_bytes);

    // 592 = 4 x 148: exactly 4 CTAs per SM in a single wave (occ 4).
    const int threads = 256;
    const int blocks  = 592;
    router_kernel<<<blocks, threads, smem_bytes>>>(h, gw, gb, out, B);
}